// round 4
// baseline (speedup 1.0000x reference)
#include <cuda_runtime.h>
#include <cuda_bf16.h>
#include <stdint.h>

#define TOKENS 8192
#define IN_F   4096
#define OUT_F  4096
#define RNK    16

// ================= device scratch (no allocs allowed) =================
__device__ float g_S[256];
__device__ float g_C[256];
__device__ float g_Qs[256];                         // alpha * Q5
__device__ float g_Aq[RNK * IN_F];                  // (alpha Q5) @ lora_A
__device__ float g_Wf[(size_t)OUT_F * IN_F];        // W' = W + lB@Aq (fp32)
__device__ float g_sx[TOKENS];
__device__ float g_sw[OUT_F];
__device__ __align__(16) char g_X1[(size_t)TOKENS * IN_F];
__device__ __align__(16) char g_X2[(size_t)TOKENS * IN_F];
__device__ __align__(16) char g_W1[(size_t)OUT_F * IN_F];
__device__ __align__(16) char g_W2[(size_t)OUT_F * IN_F];

// ================= K0/K1/K2: alpha*Q5 in rank-16 space (validated) ==========
__global__ void k_zero() { int t = threadIdx.x; g_S[t] = 0.f; g_C[t] = 0.f; }

__global__ void k_sc(const float* __restrict__ lA, const float* __restrict__ lB) {
    int t = threadIdx.x, i = t >> 4, j = t & 15;
    int k0 = blockIdx.x * 256;
    const float4* Ai = (const float4*)(lA + (size_t)i * IN_F);
    const float4* Aj = (const float4*)(lA + (size_t)j * IN_F);
    float s = 0.f;
#pragma unroll 8
    for (int k4 = k0 / 4; k4 < k0 / 4 + 64; k4++) {
        float4 a = Ai[k4], b = Aj[k4];
        s += a.x * b.x + a.y * b.y + a.z * b.z + a.w * b.w;
    }
    float c = 0.f;
#pragma unroll 4
    for (int k = k0; k < k0 + 256; k++)
        c += lB[(size_t)k * RNK + i] * lB[(size_t)k * RNK + j];
    atomicAdd(&g_S[t], s);
    atomicAdd(&g_C[t], c);
}

__global__ void k_ns() {
    __shared__ float S[256], C[256], Q[256], Rm[256], T1[256], T2[256], P[256], W2[256];
    int t = threadIdx.x, i = t >> 4, j = t & 15;
    S[t] = g_S[t]; C[t] = g_C[t];
    __syncthreads();
    W2[t] = S[i * 16 + j] * C[j * 16 + i];
    __syncthreads();
    for (int s = 128; s; s >>= 1) { if (t < s) W2[t] += W2[t + s]; __syncthreads(); }
    float alpha = sqrtf(W2[0]);
    float nrm = alpha + 1e-7f;
    Q[t] = (i == j) ? (1.f / nrm) : 0.f;
    Rm[t] = C[t] / (nrm * nrm);
    __syncthreads();
    const float ca = 3.4445f, cb = -4.775f, cc = 2.0315f;
    for (int step = 0; step < 5; step++) {
        float acc = 0.f;
#pragma unroll
        for (int k = 0; k < 16; k++) acc += S[i * 16 + k] * Rm[k * 16 + j];
        T1[t] = acc; __syncthreads();
        acc = 0.f;
#pragma unroll
        for (int k = 0; k < 16; k++) acc += T1[i * 16 + k] * T1[k * 16 + j];
        T2[t] = acc; __syncthreads();
        P[t] = cc * T2[t] + cb * T1[t] + ((i == j) ? ca : 0.f);
        __syncthreads();
        acc = 0.f;
#pragma unroll
        for (int k = 0; k < 16; k++) acc += Q[i * 16 + k] * P[k * 16 + j];
        W2[t] = acc; __syncthreads(); Q[t] = W2[t];
        acc = 0.f;
#pragma unroll
        for (int k = 0; k < 16; k++) acc += Rm[i * 16 + k] * P[k * 16 + j];
        W2[t] = acc; __syncthreads();
        acc = 0.f;
#pragma unroll
        for (int k = 0; k < 16; k++) acc += P[k * 16 + i] * W2[k * 16 + j];
        T1[t] = acc; __syncthreads(); Rm[t] = T1[t]; __syncthreads();
    }
    g_Qs[t] = alpha * Q[t];
}

// ================= K3: Aq = (alpha Q5) @ lora_A =================
__global__ void k_aq(const float* __restrict__ lA) {
    int j = blockIdx.x * 256 + threadIdx.x;
    float a[16];
#pragma unroll
    for (int s = 0; s < 16; s++) a[s] = lA[(size_t)s * IN_F + j];
#pragma unroll
    for (int r = 0; r < 16; r++) {
        float acc = 0.f;
#pragma unroll
        for (int s = 0; s < 16; s++) acc += g_Qs[r * 16 + s] * a[s];
        g_Aq[(size_t)r * IN_F + j] = acc;
    }
}

// ================= K4: W' = W + lB @ Aq (fp32 scratch) =================
__global__ void k_wfold(const float* __restrict__ W, const float* __restrict__ lB) {
    __shared__ float sAq[16 * 256];
    __shared__ float sB[64 * 16];
    int tid = threadIdx.x;
    int c0 = blockIdx.x * 256, i0 = blockIdx.y * 64;
#pragma unroll
    for (int q = 0; q < 16; q++) {
        int i = tid + 256 * q;
        sAq[i] = g_Aq[(size_t)(i >> 8) * IN_F + c0 + (i & 255)];
    }
#pragma unroll
    for (int q = 0; q < 4; q++) {
        int i = tid + 256 * q;
        sB[i] = lB[(size_t)(i0 + (i >> 4)) * RNK + (i & 15)];
    }
    __syncthreads();
    int col = c0 + tid;
    float aq[16];
#pragma unroll
    for (int r = 0; r < 16; r++) aq[r] = sAq[r * 256 + tid];
    for (int ir = 0; ir < 64; ir++) {
        size_t off = (size_t)(i0 + ir) * IN_F + col;
        float acc = W[off];
#pragma unroll
        for (int r = 0; r < 16; r++) acc += sB[ir * 16 + r] * aq[r];
        g_Wf[off] = acc;
    }
}

// ============ K5: per-row int8 2-slice quantization (x and W') ==============
__global__ void k_rowquant(const float* __restrict__ src, char* __restrict__ o1,
                           char* __restrict__ o2, float* __restrict__ sc) {
    int m = blockIdx.x, tid = threadIdx.x;
    int lane = tid & 31, warp = tid >> 5;
    const float4* xr = (const float4*)(src + (size_t)m * IN_F);
    float4 v[4];
    float mx = 0.f;
#pragma unroll
    for (int j = 0; j < 4; j++) {
        v[j] = xr[tid + 256 * j];
        mx = fmaxf(mx, fmaxf(fmaxf(fabsf(v[j].x), fabsf(v[j].y)),
                             fmaxf(fabsf(v[j].z), fabsf(v[j].w))));
    }
    __shared__ float red[8];
#pragma unroll
    for (int off = 16; off; off >>= 1)
        mx = fmaxf(mx, __shfl_xor_sync(0xffffffffu, mx, off));
    if (lane == 0) red[warp] = mx;
    __syncthreads();
    float bmax = red[0];
#pragma unroll
    for (int w = 1; w < 8; w++) bmax = fmaxf(bmax, red[w]);

    float s, inv;
    if (bmax > 0.f) { s = bmax * (1.f / 127.f); inv = 127.f / bmax; }
    else            { s = 1.f; inv = 0.f; }
    float inv2 = 128.f * inv;

    char4* p1 = (char4*)(o1 + (size_t)m * IN_F);
    char4* p2 = (char4*)(o2 + (size_t)m * IN_F);
#pragma unroll
    for (int j = 0; j < 4; j++) {
        float c[4] = { v[j].x, v[j].y, v[j].z, v[j].w };
        int a1[4], a2[4];
#pragma unroll
        for (int q = 0; q < 4; q++) {
            a1[q] = __float2int_rn(c[q] * inv);
            float r = fmaf((float)-a1[q], s, c[q]);
            a2[q] = __float2int_rn(r * inv2);
        }
        p1[tid + 256 * j] = make_char4((char)a1[0], (char)a1[1], (char)a1[2], (char)a1[3]);
        p2[tid + 256 * j] = make_char4((char)a2[0], (char)a2[1], (char)a2[2], (char)a2[3]);
    }
    if (tid == 0) sc[m] = s;
}

// ================= K6: int8 GEMM, 128x128 tile, 4-stage cp.async =============
// out[m,n] = sx[m]*sw[n]*(D11 + (X1W2 + X2W1)/128) + bias[n]
#define LDK    80                      // smem row stride bytes (64 data + 16 pad)
#define NSTG   4
#define KSTG   64
#define TILE_B (128 * LDK)             // 10240 B
#define STAGE_B (4 * TILE_B)           // 40960 B (X1,X2,W1,W2)

#define CP_ASYNC16(dst, src) \
    asm volatile("cp.async.cg.shared.global [%0], [%1], 16;" :: "r"(dst), "l"(src))
#define CP_COMMIT() asm volatile("cp.async.commit_group;" ::: "memory")
#define CP_WAIT2()  asm volatile("cp.async.wait_group 2;" ::: "memory")

__device__ __forceinline__ uint32_t smem_u32(const void* p) {
    uint32_t a;
    asm("{ .reg .u64 t; cvta.to.shared.u64 t, %1; cvt.u32.u64 %0, t; }" : "=r"(a) : "l"(p));
    return a;
}

__device__ __forceinline__ void mma_i8(int* c, const uint32_t* a, const uint32_t* b) {
    asm volatile(
        "mma.sync.aligned.m16n8k32.row.col.s32.s8.s8.s32 "
        "{%0,%1,%2,%3}, {%4,%5,%6,%7}, {%8,%9}, {%0,%1,%2,%3};\n"
        : "+r"(c[0]), "+r"(c[1]), "+r"(c[2]), "+r"(c[3])
        : "r"(a[0]), "r"(a[1]), "r"(a[2]), "r"(a[3]), "r"(b[0]), "r"(b[1]));
}

__device__ __forceinline__ void mma_step_i8(
    const char* sX1, const char* sX2, const char* sW1, const char* sW2,
    int ks, int wm, int wn, int g, int tg,
    int acc1[4][4][4], int acc2[4][4][4])
{
    uint32_t a1[4][4], a2[4][4], b1[4][2], b2[4][2];
#pragma unroll
    for (int mt = 0; mt < 4; mt++) {
        int o0 = (wm * 64 + mt * 16 + g) * LDK + ks + tg * 4;
        int o1 = o0 + 8 * LDK;
        a1[mt][0] = *(const uint32_t*)(sX1 + o0);
        a1[mt][1] = *(const uint32_t*)(sX1 + o1);
        a1[mt][2] = *(const uint32_t*)(sX1 + o0 + 16);
        a1[mt][3] = *(const uint32_t*)(sX1 + o1 + 16);
        a2[mt][0] = *(const uint32_t*)(sX2 + o0);
        a2[mt][1] = *(const uint32_t*)(sX2 + o1);
        a2[mt][2] = *(const uint32_t*)(sX2 + o0 + 16);
        a2[mt][3] = *(const uint32_t*)(sX2 + o1 + 16);
    }
#pragma unroll
    for (int nt = 0; nt < 4; nt++) {
        int ob = (wn * 32 + nt * 8 + g) * LDK + ks + tg * 4;
        b1[nt][0] = *(const uint32_t*)(sW1 + ob);
        b1[nt][1] = *(const uint32_t*)(sW1 + ob + 16);
        b2[nt][0] = *(const uint32_t*)(sW2 + ob);
        b2[nt][1] = *(const uint32_t*)(sW2 + ob + 16);
    }
#pragma unroll
    for (int mt = 0; mt < 4; mt++) {
#pragma unroll
        for (int nt = 0; nt < 4; nt++) {
            mma_i8(acc1[mt][nt], a1[mt], b1[nt]);   // X1*W1
            mma_i8(acc2[mt][nt], a1[mt], b2[nt]);   // X1*W2
            mma_i8(acc2[mt][nt], a2[mt], b1[nt]);   // X2*W1
        }
    }
}

__global__ void __launch_bounds__(256, 1)
k_gemm(const float* __restrict__ bias, float* __restrict__ out)
{
    extern __shared__ __align__(128) char dsm[];
    uint32_t sbase = smem_u32(dsm);

    int tid  = threadIdx.x;
    int warp = tid >> 5, lane = tid & 31;
    int wm = warp & 1, wn = warp >> 1;
    int g  = lane >> 2, tg = lane & 3;

    int bx = blockIdx.x;
    int m0 = (bx >> 5) * 128;
    int n0 = (bx & 31) * 128;

    // per-thread cp.async: 8 x 16B chunks per stage (4 tiles x 128 rows x 64B)
    const char* gsrc[8];
    uint32_t sdst[8];
    {
        const char* basep[4] = { g_X1, g_X2, g_W1, g_W2 };
#pragma unroll
        for (int j = 0; j < 8; j++) {
            int idx  = tid + 256 * j;       // 0..2047
            int tile = idx >> 9;            // 0..3
            int c    = idx & 511;
            int row  = c >> 2;              // 0..127
            int c4   = c & 3;               // 16B chunk in 64B row
            int grow = (tile < 2 ? m0 : n0) + row;
            gsrc[j] = basep[tile] + (size_t)grow * IN_F + c4 * 16;
            sdst[j] = sbase + tile * TILE_B + row * LDK + c4 * 16;
        }
    }

    int acc1[4][4][4], acc2[4][4][4];
#pragma unroll
    for (int a = 0; a < 4; a++)
#pragma unroll
        for (int b = 0; b < 4; b++)
#pragma unroll
            for (int c = 0; c < 4; c++) { acc1[a][b][c] = 0; acc2[a][b][c] = 0; }

    const int NKB = IN_F / KSTG;   // 64

    // prologue
#pragma unroll
    for (int s = 0; s < NSTG - 1; s++) {
        uint32_t so = s * STAGE_B;
        long ko = (long)s * KSTG;
#pragma unroll
        for (int j = 0; j < 8; j++) CP_ASYNC16(sdst[j] + so, gsrc[j] + ko);
        CP_COMMIT();
    }

    for (int kb = 0; kb < NKB; kb++) {
        CP_WAIT2();
        __syncthreads();

        if (kb + NSTG - 1 < NKB) {
            uint32_t so = ((kb + NSTG - 1) & (NSTG - 1)) * STAGE_B;
            long ko = (long)(kb + NSTG - 1) * KSTG;
#pragma unroll
            for (int j = 0; j < 8; j++) CP_ASYNC16(sdst[j] + so, gsrc[j] + ko);
        }
        CP_COMMIT();

        const char* stg = dsm + (kb & (NSTG - 1)) * STAGE_B;
        const char* sX1 = stg;
        const char* sX2 = stg + TILE_B;
        const char* sW1 = stg + 2 * TILE_B;
        const char* sW2 = stg + 3 * TILE_B;
        mma_step_i8(sX1, sX2, sW1, sW2, 0,  wm, wn, g, tg, acc1, acc2);
        mma_step_i8(sX1, sX2, sW1, sW2, 32, wm, wn, g, tg, acc1, acc2);
        __syncthreads();
    }

    // epilogue: dequant + bias
#pragma unroll
    for (int nt = 0; nt < 4; nt++) {
        int c = n0 + wn * 32 + nt * 8 + tg * 2;
        float b0 = __ldg(&bias[c]);
        float b1v = __ldg(&bias[c + 1]);
        float sw0 = __ldg(&g_sw[c]) * 0.0078125f;
        float sw1 = __ldg(&g_sw[c + 1]) * 0.0078125f;
#pragma unroll
        for (int mt = 0; mt < 4; mt++) {
            int r0 = m0 + wm * 64 + mt * 16 + g;
            float sx0 = g_sx[r0];
            float sx1 = g_sx[r0 + 8];
            long long t00 = (((long long)acc1[mt][nt][0]) << 7) + acc2[mt][nt][0];
            long long t01 = (((long long)acc1[mt][nt][1]) << 7) + acc2[mt][nt][1];
            long long t10 = (((long long)acc1[mt][nt][2]) << 7) + acc2[mt][nt][2];
            long long t11 = (((long long)acc1[mt][nt][3]) << 7) + acc2[mt][nt][3];
            float2 v0, v1;
            v0.x = fmaf((float)t00, sx0 * sw0, b0);
            v0.y = fmaf((float)t01, sx0 * sw1, b1v);
            v1.x = fmaf((float)t10, sx1 * sw0, b0);
            v1.y = fmaf((float)t11, sx1 * sw1, b1v);
            *(float2*)&out[(size_t)r0 * OUT_F + c]       = v0;
            *(float2*)&out[(size_t)(r0 + 8) * OUT_F + c] = v1;
        }
    }
}

// ================= launch =================
extern "C" void kernel_launch(void* const* d_in, const int* in_sizes, int n_in,
                              void* d_out, int out_size) {
    const float* x    = (const float*)d_in[0];
    const float* W    = (const float*)d_in[1];
    const float* bias = (const float*)d_in[2];
    const float* lA   = (const float*)d_in[3];
    const float* lB   = (const float*)d_in[4];
    float* out = (float*)d_out;

    k_zero<<<1, 256>>>();
    k_sc<<<16, 256>>>(lA, lB);
    k_ns<<<1, 256>>>();
    k_aq<<<16, 256>>>(lA);
    {
        dim3 g(IN_F / 256, OUT_F / 64);
        k_wfold<<<g, 256>>>(W, lB);
    }
    // device-global pointers for quant outputs
    char *pX1, *pX2, *pW1, *pW2;
    float *psx, *psw, *pWf;
    cudaGetSymbolAddress((void**)&pX1, g_X1);
    cudaGetSymbolAddress((void**)&pX2, g_X2);
    cudaGetSymbolAddress((void**)&pW1, g_W1);
    cudaGetSymbolAddress((void**)&pW2, g_W2);
    cudaGetSymbolAddress((void**)&psx, g_sx);
    cudaGetSymbolAddress((void**)&psw, g_sw);
    cudaGetSymbolAddress((void**)&pWf, g_Wf);

    k_rowquant<<<OUT_F, 256>>>(pWf, pW1, pW2, psw);
    k_rowquant<<<TOKENS, 256>>>(x, pX1, pX2, psx);

    static int smem_set = 0;
    int smem_sz = NSTG * STAGE_B;   // 163840
    if (!smem_set) {
        cudaFuncSetAttribute(k_gemm, cudaFuncAttributeMaxDynamicSharedMemorySize, smem_sz);
        smem_set = 1;
    }
    int nblocks = (TOKENS / 128) * (OUT_F / 128);   // 2048
    k_gemm<<<nblocks, 256, smem_sz>>>(bias, out);
}

// round 5
// speedup vs baseline: 2.6161x; 2.6161x over previous
#include <cuda_runtime.h>
#include <cuda_bf16.h>
#include <stdint.h>

#define TOKENS 8192
#define IN_F   4096
#define OUT_F  4096
#define RNK    16

// ================= device scratch (no allocs allowed) =================
__device__ float g_S[256];
__device__ float g_C[256];
__device__ float g_Qs[256];                         // alpha * Q5
__device__ float g_Aq[RNK * IN_F];                  // (alpha Q5) @ lora_A
__device__ __align__(1024) __nv_bfloat16 g_Xh[(size_t)TOKENS * IN_F];
__device__ __align__(1024) __nv_bfloat16 g_Xl[(size_t)TOKENS * IN_F];
__device__ __align__(1024) __nv_bfloat16 g_Wh[(size_t)OUT_F * IN_F];
__device__ __align__(1024) __nv_bfloat16 g_Wl[(size_t)OUT_F * IN_F];

// ================= K0/K1/K2: alpha*Q5 in rank-16 space (validated) ==========
__global__ void k_zero() { int t = threadIdx.x; g_S[t] = 0.f; g_C[t] = 0.f; }

__global__ void k_sc(const float* __restrict__ lA, const float* __restrict__ lB) {
    int t = threadIdx.x, i = t >> 4, j = t & 15;
    int k0 = blockIdx.x * 256;
    const float4* Ai = (const float4*)(lA + (size_t)i * IN_F);
    const float4* Aj = (const float4*)(lA + (size_t)j * IN_F);
    float s = 0.f;
#pragma unroll 8
    for (int k4 = k0 / 4; k4 < k0 / 4 + 64; k4++) {
        float4 a = Ai[k4], b = Aj[k4];
        s += a.x * b.x + a.y * b.y + a.z * b.z + a.w * b.w;
    }
    float c = 0.f;
#pragma unroll 4
    for (int k = k0; k < k0 + 256; k++)
        c += lB[(size_t)k * RNK + i] * lB[(size_t)k * RNK + j];
    atomicAdd(&g_S[t], s);
    atomicAdd(&g_C[t], c);
}

__global__ void k_ns() {
    __shared__ float S[256], C[256], Q[256], Rm[256], T1[256], T2[256], P[256], W2[256];
    int t = threadIdx.x, i = t >> 4, j = t & 15;
    S[t] = g_S[t]; C[t] = g_C[t];
    __syncthreads();
    W2[t] = S[i * 16 + j] * C[j * 16 + i];
    __syncthreads();
    for (int s = 128; s; s >>= 1) { if (t < s) W2[t] += W2[t + s]; __syncthreads(); }
    float alpha = sqrtf(W2[0]);
    float nrm = alpha + 1e-7f;
    Q[t] = (i == j) ? (1.f / nrm) : 0.f;
    Rm[t] = C[t] / (nrm * nrm);
    __syncthreads();
    const float ca = 3.4445f, cb = -4.775f, cc = 2.0315f;
    for (int step = 0; step < 5; step++) {
        float acc = 0.f;
#pragma unroll
        for (int k = 0; k < 16; k++) acc += S[i * 16 + k] * Rm[k * 16 + j];
        T1[t] = acc; __syncthreads();
        acc = 0.f;
#pragma unroll
        for (int k = 0; k < 16; k++) acc += T1[i * 16 + k] * T1[k * 16 + j];
        T2[t] = acc; __syncthreads();
        P[t] = cc * T2[t] + cb * T1[t] + ((i == j) ? ca : 0.f);
        __syncthreads();
        acc = 0.f;
#pragma unroll
        for (int k = 0; k < 16; k++) acc += Q[i * 16 + k] * P[k * 16 + j];
        W2[t] = acc; __syncthreads(); Q[t] = W2[t];
        acc = 0.f;
#pragma unroll
        for (int k = 0; k < 16; k++) acc += Rm[i * 16 + k] * P[k * 16 + j];
        W2[t] = acc; __syncthreads();
        acc = 0.f;
#pragma unroll
        for (int k = 0; k < 16; k++) acc += P[k * 16 + i] * W2[k * 16 + j];
        T1[t] = acc; __syncthreads(); Rm[t] = T1[t]; __syncthreads();
    }
    g_Qs[t] = alpha * Q[t];
}

// ================= K3: Aq = (alpha Q5) @ lora_A =================
__global__ void k_aq(const float* __restrict__ lA) {
    int j = blockIdx.x * 256 + threadIdx.x;
    float a[16];
#pragma unroll
    for (int s = 0; s < 16; s++) a[s] = lA[(size_t)s * IN_F + j];
#pragma unroll
    for (int r = 0; r < 16; r++) {
        float acc = 0.f;
#pragma unroll
        for (int s = 0; s < 16; s++) acc += g_Qs[r * 16 + s] * a[s];
        g_Aq[(size_t)r * IN_F + j] = acc;
    }
}

// ============ K4: W' = W + lB @ Aq; split to bf16 hi/lo =====================
__global__ void k_wprep(const float* __restrict__ W, const float* __restrict__ lB) {
    __shared__ float sAq[16 * 256];
    __shared__ float sB[64 * 16];
    int tid = threadIdx.x;
    int c0 = blockIdx.x * 256, i0 = blockIdx.y * 64;
#pragma unroll
    for (int q = 0; q < 16; q++) {
        int i = tid + 256 * q;
        sAq[i] = g_Aq[(size_t)(i >> 8) * IN_F + c0 + (i & 255)];
    }
#pragma unroll
    for (int q = 0; q < 4; q++) {
        int i = tid + 256 * q;
        sB[i] = lB[(size_t)(i0 + (i >> 4)) * RNK + (i & 15)];
    }
    __syncthreads();
    int col = c0 + tid;
    float aq[16];
#pragma unroll
    for (int r = 0; r < 16; r++) aq[r] = sAq[r * 256 + tid];
    for (int ir = 0; ir < 64; ir++) {
        size_t off = (size_t)(i0 + ir) * IN_F + col;
        float acc = W[off];
#pragma unroll
        for (int r = 0; r < 16; r++) acc += sB[ir * 16 + r] * aq[r];
        __nv_bfloat16 h = __float2bfloat16(acc);
        g_Wh[off] = h;
        g_Wl[off] = __float2bfloat16(acc - __bfloat162float(h));
    }
}

// ================= K5: split x into bf16 hi/lo =================
__global__ void k_xsplit(const float* __restrict__ x) {
    size_t i = (size_t)blockIdx.x * 256 + threadIdx.x;   // float4 index
    float4 v = ((const float4*)x)[i];
    __nv_bfloat16 h0 = __float2bfloat16(v.x), h1 = __float2bfloat16(v.y);
    __nv_bfloat16 h2 = __float2bfloat16(v.z), h3 = __float2bfloat16(v.w);
    __nv_bfloat162 a; a.x = h0; a.y = h1;
    __nv_bfloat162 b; b.x = h2; b.y = h3;
    ((__nv_bfloat162*)g_Xh)[i * 2]     = a;
    ((__nv_bfloat162*)g_Xh)[i * 2 + 1] = b;
    __nv_bfloat162 c, d;
    c.x = __float2bfloat16(v.x - __bfloat162float(h0));
    c.y = __float2bfloat16(v.y - __bfloat162float(h1));
    d.x = __float2bfloat16(v.z - __bfloat162float(h2));
    d.y = __float2bfloat16(v.w - __bfloat162float(h3));
    ((__nv_bfloat162*)g_Xl)[i * 2]     = c;
    ((__nv_bfloat162*)g_Xl)[i * 2 + 1] = d;
}

// ======== K6: bf16 GEMM, 128x128 tile, ldmatrix + swizzle, 2 CTAs/SM ========
// out = [Xh+Xl] @ [Wh+Wl]^T + bias  (3 terms: XhWh + XhWl + XlWh)
// Tile: 128 rows x 32 bf16 = 64B/row, swizzle sel = chunk ^ ((row>>1)&3).
#define NSTG   3
#define KSTG   32
#define TILE_B 8192                    // 128 * 64B
#define STAGE_B (4 * TILE_B)           // 32768 (Xh,Xl,Wh,Wl)

#define CP_ASYNC16(dst, src) \
    asm volatile("cp.async.cg.shared.global [%0], [%1], 16;" :: "r"(dst), "l"(src))
#define CP_COMMIT() asm volatile("cp.async.commit_group;" ::: "memory")
#define CP_WAIT1()  asm volatile("cp.async.wait_group 1;" ::: "memory")

__device__ __forceinline__ uint32_t smem_u32(const void* p) {
    uint32_t a;
    asm("{ .reg .u64 t; cvta.to.shared.u64 t, %1; cvt.u32.u64 %0, t; }" : "=r"(a) : "l"(p));
    return a;
}

__device__ __forceinline__ void ldsm4(uint32_t* r, uint32_t addr) {
    asm volatile("ldmatrix.sync.aligned.m8n8.x4.shared.b16 {%0,%1,%2,%3}, [%4];"
        : "=r"(r[0]), "=r"(r[1]), "=r"(r[2]), "=r"(r[3]) : "r"(addr));
}

__device__ __forceinline__ void mma16816(float* c, const uint32_t* a,
                                         uint32_t b0, uint32_t b1) {
    asm volatile(
        "mma.sync.aligned.m16n8k16.row.col.f32.bf16.bf16.f32 "
        "{%0,%1,%2,%3}, {%4,%5,%6,%7}, {%8,%9}, {%0,%1,%2,%3};\n"
        : "+f"(c[0]), "+f"(c[1]), "+f"(c[2]), "+f"(c[3])
        : "r"(a[0]), "r"(a[1]), "r"(a[2]), "r"(a[3]), "r"(b0), "r"(b1));
}

__global__ void __launch_bounds__(256, 2)
k_gemm(const float* __restrict__ bias, float* __restrict__ out)
{
    extern __shared__ __align__(128) char dsm[];
    uint32_t sbase = smem_u32(dsm);

    int tid  = threadIdx.x;
    int warp = tid >> 5, lane = tid & 31;
    int wm = warp & 1, wn = warp >> 1;     // 2(m) x 4(n) warps, warp tile 64x32
    int g  = lane >> 2, tg = lane & 3;

    int bx = blockIdx.x;
    int m0 = (bx >> 5) * 128;
    int n0 = (bx & 31) * 128;

    // ---- ldmatrix per-thread base addresses (within a tile) ----
    // lane row = l&15, k-half = l>>4; addr(row,chunk)=row*64+((chunk^((row>>1)&3))<<4)
    int lrow = lane & 15, lhalf = lane >> 4;
    uint32_t baseA[4], baseB[2];
#pragma unroll
    for (int mt = 0; mt < 4; mt++) {
        int r = wm * 64 + mt * 16 + lrow;
        baseA[mt] = (uint32_t)(r * 64 + ((lhalf ^ ((r >> 1) & 3)) << 4));
    }
#pragma unroll
    for (int p = 0; p < 2; p++) {
        int r = wn * 32 + p * 16 + lrow;
        baseB[p] = (uint32_t)(r * 64 + ((lhalf ^ ((r >> 1) & 3)) << 4));
    }

    // ---- cp.async assignments: 8 x 16B chunks per thread per stage ----
    const char* gsrc[8];
    uint32_t sdst[8];
    {
        const char* basep[4] = { (const char*)g_Xh, (const char*)g_Xl,
                                 (const char*)g_Wh, (const char*)g_Wl };
#pragma unroll
        for (int j = 0; j < 8; j++) {
            int idx  = tid + 256 * j;       // 0..2047
            int tile = idx >> 9;            // 0..3
            int c    = idx & 511;
            int row  = c >> 2;              // 0..127
            int c4   = c & 3;               // 16B chunk in 64B row
            int grow = (tile < 2 ? m0 : n0) + row;
            gsrc[j] = basep[tile] + ((size_t)grow * IN_F + c4 * 8) * 2;
            sdst[j] = sbase + tile * TILE_B + row * 64
                    + (uint32_t)(((c4 ^ ((row >> 1) & 3)) << 4));
        }
    }

    float acc[4][4][4];
#pragma unroll
    for (int a = 0; a < 4; a++)
#pragma unroll
        for (int b = 0; b < 4; b++)
#pragma unroll
            for (int c = 0; c < 4; c++) acc[a][b][c] = 0.f;

    const int NKB = IN_F / KSTG;   // 128

    // prologue: stages 0,1
#pragma unroll
    for (int s = 0; s < NSTG - 1; s++) {
        uint32_t so = s * STAGE_B;
        long ko = (long)s * (KSTG * 2);
#pragma unroll
        for (int j = 0; j < 8; j++) CP_ASYNC16(sdst[j] + so, gsrc[j] + ko);
        CP_COMMIT();
    }

    for (int kb = 0; kb < NKB; kb++) {
        CP_WAIT1();
        __syncthreads();

        if (kb + NSTG - 1 < NKB) {
            int st = kb + NSTG - 1;
            uint32_t so = (uint32_t)((st % NSTG) * STAGE_B);
            long ko = (long)st * (KSTG * 2);
#pragma unroll
            for (int j = 0; j < 8; j++) CP_ASYNC16(sdst[j] + so, gsrc[j] + ko);
        }
        CP_COMMIT();

        uint32_t stg = sbase + (uint32_t)((kb % NSTG) * STAGE_B);
        uint32_t sXh = stg, sXl = stg + TILE_B;
        uint32_t sWh = stg + 2 * TILE_B, sWl = stg + 3 * TILE_B;

#pragma unroll
        for (int ks = 0; ks < 2; ks++) {
            uint32_t kx = ks ? 32u : 0u;   // flips chunk-sel bit (k-half pair)
            uint32_t Ah[16], Bh[8], Tt[16];
#pragma unroll
            for (int mt = 0; mt < 4; mt++) ldsm4(Ah + 4 * mt, sXh + (baseA[mt] ^ kx));
#pragma unroll
            for (int p = 0; p < 2; p++)    ldsm4(Bh + 4 * p,  sWh + (baseB[p] ^ kx));
#pragma unroll
            for (int mt = 0; mt < 4; mt++)
#pragma unroll
                for (int nt = 0; nt < 4; nt++) {
                    int p = nt >> 1, o = nt & 1;
                    mma16816(acc[mt][nt], Ah + 4 * mt, Bh[p * 4 + o], Bh[p * 4 + 2 + o]);
                }
            // hi * lo
#pragma unroll
            for (int p = 0; p < 2; p++)    ldsm4(Tt + 4 * p,  sWl + (baseB[p] ^ kx));
#pragma unroll
            for (int mt = 0; mt < 4; mt++)
#pragma unroll
                for (int nt = 0; nt < 4; nt++) {
                    int p = nt >> 1, o = nt & 1;
                    mma16816(acc[mt][nt], Ah + 4 * mt, Tt[p * 4 + o], Tt[p * 4 + 2 + o]);
                }
            // lo * hi
#pragma unroll
            for (int mt = 0; mt < 4; mt++) ldsm4(Tt + 4 * mt, sXl + (baseA[mt] ^ kx));
#pragma unroll
            for (int mt = 0; mt < 4; mt++)
#pragma unroll
                for (int nt = 0; nt < 4; nt++) {
                    int p = nt >> 1, o = nt & 1;
                    mma16816(acc[mt][nt], Tt + 4 * mt, Bh[p * 4 + o], Bh[p * 4 + 2 + o]);
                }
        }
        __syncthreads();
    }

    // epilogue: + bias, store fp32
#pragma unroll
    for (int nt = 0; nt < 4; nt++) {
        int c = n0 + wn * 32 + nt * 8 + tg * 2;
        float b0 = __ldg(&bias[c]);
        float b1 = __ldg(&bias[c + 1]);
#pragma unroll
        for (int mt = 0; mt < 4; mt++) {
            int r0 = m0 + wm * 64 + mt * 16 + g;
            float2 v0, v1;
            v0.x = acc[mt][nt][0] + b0;
            v0.y = acc[mt][nt][1] + b1;
            v1.x = acc[mt][nt][2] + b0;
            v1.y = acc[mt][nt][3] + b1;
            *(float2*)&out[(size_t)r0 * OUT_F + c]       = v0;
            *(float2*)&out[(size_t)(r0 + 8) * OUT_F + c] = v1;
        }
    }
}

// ================= launch =================
extern "C" void kernel_launch(void* const* d_in, const int* in_sizes, int n_in,
                              void* d_out, int out_size) {
    const float* x    = (const float*)d_in[0];
    const float* W    = (const float*)d_in[1];
    const float* bias = (const float*)d_in[2];
    const float* lA   = (const float*)d_in[3];
    const float* lB   = (const float*)d_in[4];
    float* out = (float*)d_out;

    k_zero<<<1, 256>>>();
    k_sc<<<16, 256>>>(lA, lB);
    k_ns<<<1, 256>>>();
    k_aq<<<16, 256>>>(lA);
    {
        dim3 g(IN_F / 256, OUT_F / 64);
        k_wprep<<<g, 256>>>(W, lB);
    }
    k_xsplit<<<(TOKENS * (IN_F / 4)) / 256, 256>>>(x);

    static int smem_set = 0;
    int smem_sz = NSTG * STAGE_B;   // 98304
    if (!smem_set) {
        cudaFuncSetAttribute(k_gemm, cudaFuncAttributeMaxDynamicSharedMemorySize, smem_sz);
        smem_set = 1;
    }
    int nblocks = (TOKENS / 128) * (OUT_F / 128);   // 2048
    k_gemm<<<nblocks, 256, smem_sz>>>(bias, out);
}